// round 12
// baseline (speedup 1.0000x reference)
#include <cuda_runtime.h>

#define W 512
#define H 512
#define NPLANES 96
#define SKEW 3
#define NWARPS 8             // 8 warps; each runs 2 bands (w and w+8)
#define NBANDS 16
#define CH 16                // columns per sync chunk
#define LAG 96               // 32 rows * SKEW: producer lead needed by consumer
#define NSTEP_PAD 608        // ceil((512 + 3*31)=605) to multiple of CH
#define NCHUNK (NSTEP_PAD / CH)

// Floyd-Steinberg 1-bit error diffusion.
// R3's schedule and inner-loop arithmetic are preserved byte-for-byte; two
// contention-only changes:
//  (1) 8 warps x 2 bands instead of 16 warps x 1. Band b still starts at
//      ~112*b steps (warp w is free for band w+8 before the cascade allows it
//      to start), so the critical path is identical — but average spinners
//      drop ~10.6 -> ~2.6 and total warps halve, unloading the smem crossbar
//      (spin polls are LDS; crossbar binds ~1 op/4cyc at nw>=4) and the issue
//      slots the ~5 active warps need. R10/R11 proved alternate waiters lose
//      on wake latency; raw volatile spin stays.
//  (2) Guarded stores flattened to single-statement ifs -> predicated
//      @P STG/STS, no per-step BSSY/BSYNC reconvergence.
__global__ void __launch_bounds__(NWARPS * 32, 1)
fs_dither_kernel(const float* __restrict__ x, float* __restrict__ out) {
    __shared__ float errbuf[NBANDS][W];
    __shared__ float zbuf[W];
    __shared__ volatile unsigned progress[NBANDS];

    const int tid = threadIdx.x;
    const int w = tid >> 5;
    const int lane = tid & 31;
    const int plane = blockIdx.x;

    const float* __restrict__ xp = x + (size_t)plane * (H * W);
    float* __restrict__ op = out + (size_t)plane * (H * W);

    for (int i = tid; i < W; i += NWARPS * 32) zbuf[i] = 0.0f;
    for (int i = tid; i < NBANDS; i += NWARPS * 32) progress[i] = 0u;
    __syncthreads();

    const bool is31 = (lane == 31);

    for (int half = 0; half < 2; ++half) {
        const int band = w + half * NWARPS;          // 0..15
        const float* __restrict__ prevrow = (band == 0) ? zbuf : errbuf[band - 1];
        float* __restrict__ myrow = errbuf[band];
        const int row = band * 32 + lane;
        const float* __restrict__ xrow = xp + (size_t)row * W;
        float* __restrict__ orow = op + (size_t)row * W;

        // Delay line: at step t lane l consumes e_ur=r2, e_u=r3, e_ul=r4
        // (row-above errs at cols c+1, c, c-1); r1 is the 3-ahead value
        // (lane 0: prevrow[t+3]).
        float r1 = 0.0f, r2 = 0.0f, r3 = 0.0f, r4 = 0.0f;
        float left = 0.0f;

        int t = 0;
        for (int k = 0; k < NCHUNK; ++k) {
            if (band != 0) {
                unsigned need = (unsigned)(t + CH + LAG);
                if (need > NSTEP_PAD) need = NSTEP_PAD;
                while (progress[band - 1] < need) { /* spin (proven fastest) */ }
            }
            __syncwarp();
            __threadfence_block();   // acquire: producer's STS now visible

            if (k == 0 && lane == 0) {
                // prev[-1]=0 (pad), prev[0..2]; gated by first poll (need>=112)
                r4 = 0.0f;
                r3 = prevrow[0];
                r2 = prevrow[1];
                r1 = prevrow[2];
            }

            #pragma unroll 4
            for (int i = 0; i < CH; ++i, ++t) {
                const int c = t - SKEW * lane;
                const bool active = ((unsigned)c < (unsigned)W);
                const float e_ur = r2, e_u = r3, e_ul = r4;

                // Clamped-address load keeps inactive lanes branch-free.
                int cl = c < 0 ? 0 : (c > W - 1 ? W - 1 : c);
                float xv = __ldg(xrow + cl);

                // x = clip(x,-1,1); x01 = (x+1)/2  (exact, matches reference)
                xv = fminf(fmaxf(xv, -1.0f), 1.0f);
                float x01 = __fmul_rn(__fadd_rn(xv, 1.0f), 0.5f);

                // up = (1/16*e_ul + 5/16*e_u) + 3/16*e_ur (reference order)
                float u = __fadd_rn(__fadd_rn(__fmul_rn(0.0625f, e_ul),
                                              __fmul_rn(0.3125f, e_u)),
                                    __fmul_rn(0.1875f, e_ur));
                float pre = __fadd_rn(x01, u);
                float raw = __fadd_rn(pre, __fmul_rn(0.4375f, left));
                float val = fminf(fmaxf(raw, 0.0f), 1.0f);

                // q = round-half-even(val), val in [0,1]  <=>  raw > 0.5.
                // d = 0.5 - raw has exact sign (Sterbenz in [0.25,1]); tie->q=0.
                float d = __fadd_rn(0.5f, -raw);
                unsigned s = (unsigned)(__float_as_int(d) >> 31);
                // err = val - q exactly: val + (-1.0f masked); Sterbenz-exact.
                float err = __fadd_rn(val, __uint_as_float(s & 0xBF800000u));
                err = active ? err : 0.0f;   // inactive lanes feed zero padding

                // Flat single-statement guards -> @P STG / @P STS (no BSSY).
                float ov = __uint_as_float(0xBF800000u ^ (s & 0x80000000u));
                if (active) orow[c] = ov;                // output = 2q-1
                if (active & is31) myrow[c] = err;       // band handoff

                left = err;

                // Cross-lane propagation (2 steps of slack before use).
                float sh = __shfl_up_sync(0xFFFFFFFFu, err, 1);
                const int pi = t + SKEW;
                float pv = (pi < W) ? prevrow[pi] : 0.0f;  // broadcast LDS
                if (lane == 0) sh = pv;                    // SEL, no branch
                r4 = r3; r3 = r2; r2 = r1; r1 = sh;
            }

            if (lane == 31) {
                __threadfence_block();     // release: STS before counter
                progress[band] = (unsigned)t;
            }
        }
    }
}

extern "C" void kernel_launch(void* const* d_in, const int* in_sizes, int n_in,
                              void* d_out, int out_size) {
    (void)in_sizes; (void)n_in; (void)out_size;
    const float* x = (const float*)d_in[0];
    float* out = (float*)d_out;
    fs_dither_kernel<<<NPLANES, NWARPS * 32>>>(x, out);
}

// round 13
// speedup vs baseline: 1.7985x; 1.7985x over previous
#include <cuda_runtime.h>

#define W 512
#define H 512
#define NPLANES 96
#define SKEW 3
#define NWARPS 16            // one band (32 rows) per warp, whole plane per block
#define CH 16                // columns per sync chunk
#define LAG 96               // 32 rows * SKEW: producer lead needed by consumer
#define NSTEP_PAD 608        // ceil((512 + 3*31)=605 to multiple of CH)
#define NCHUNK (NSTEP_PAD / CH)

// Floyd-Steinberg 1-bit error diffusion.
// Block = one 512x512 plane, 16 warps. Warp w owns rows [32w, 32w+32).
// Within a warp: anti-diagonal wavefront, lane l handles row 32w+l at
// column c = t - 3l (skew 3 -> 1 full step of slack over the 26-cyc SHFL).
// Across warps: band pipeline; warp w-1's lane-31 err row is handed to
// warp w through SMEM in 16-column chunks guarded by a volatile progress
// counter + __threadfence_block (release/acquire within the CTA).
//
// NOTE: byte-for-byte resubmission of the Round-3 kernel (260us). Rounds 4-12
// tried 7 "improvements" (nanosleep/mbarrier/clock-paced waits, bulk-sync,
// branch-free stores, skew-2, 8-warp) — all regressed 35-80% despite models
// predicting neutral-or-better. This run distinguishes fragile-compiler-
// scheduling (reproduces ~260) from measurement tail (lands ~400).
__global__ void __launch_bounds__(NWARPS * 32, 1)
fs_dither_kernel(const float* __restrict__ x, float* __restrict__ out) {
    __shared__ float errbuf[NWARPS][W];
    __shared__ float zbuf[W];
    __shared__ volatile unsigned progress[NWARPS];

    const int tid = threadIdx.x;
    const int w = tid >> 5;
    const int lane = tid & 31;
    const int plane = blockIdx.x;

    const float* __restrict__ xp = x + (size_t)plane * (H * W);
    float* __restrict__ op = out + (size_t)plane * (H * W);

    for (int i = tid; i < W; i += NWARPS * 32) zbuf[i] = 0.0f;
    if (tid < NWARPS) progress[tid] = 0u;
    __syncthreads();

    const float* __restrict__ prevrow = (w == 0) ? zbuf : errbuf[w - 1];
    float* __restrict__ myrow = errbuf[w];

    const int row = w * 32 + lane;
    const float* __restrict__ xrow = xp + (size_t)row * W;
    float* __restrict__ orow = op + (size_t)row * W;

    // Delay line: at step t lane l consumes e_ur=r2, e_u=r3, e_ul=r4, which are
    // the row-above errs at columns c+1, c, c-1 (c = t - 3*lane); r1 is the
    // 3-ahead prefetch (lane 0: from prevrow[t+3], lanes>0: shfl from above).
    float r1 = 0.0f, r2 = 0.0f, r3 = 0.0f, r4 = 0.0f;
    float left = 0.0f;

    int t = 0;
    for (int k = 0; k < NCHUNK; ++k) {
        if (w != 0) {
            unsigned need = (unsigned)(t + CH + LAG);
            if (need > NSTEP_PAD) need = NSTEP_PAD;
            while (progress[w - 1] < need) { /* spin */ }
        }
        __syncwarp();
        __threadfence_block();   // acquire: producer's STS now visible

        if (k == 0 && lane == 0) {
            // prev[-1]=0 (pad), prev[0..2]; gated by the first poll (need>=112>95)
            r4 = 0.0f;
            r3 = prevrow[0];
            r2 = prevrow[1];
            r1 = prevrow[2];
        }

        #pragma unroll
        for (int i = 0; i < CH; ++i, ++t) {
            const int c = t - SKEW * lane;
            const bool active = ((unsigned)c < (unsigned)W);
            const float e_ur = r2, e_u = r3, e_ul = r4;

            // Clamped-address load keeps inactive lanes branch-free (L1-hit).
            int cl = c < 0 ? 0 : (c > W - 1 ? W - 1 : c);
            float xv = __ldg(xrow + cl);

            // x = clip(x,-1,1); x01 = (x+1)/2  (exact, matches reference)
            xv = fminf(fmaxf(xv, -1.0f), 1.0f);
            float x01 = __fmul_rn(__fadd_rn(xv, 1.0f), 0.5f);

            // up = (1/16*e_ul + 5/16*e_u) + 3/16*e_ur  (reference order, no FMA)
            float u = __fadd_rn(__fadd_rn(__fmul_rn(0.0625f, e_ul),
                                          __fmul_rn(0.3125f, e_u)),
                                __fmul_rn(0.1875f, e_ur));
            float pre = __fadd_rn(x01, u);
            float raw = __fadd_rn(pre, __fmul_rn(0.4375f, left));
            float val = fminf(fmaxf(raw, 0.0f), 1.0f);

            // q = round-half-even(val), val in [0,1]  <=>  raw > 0.5.
            // d = 0.5 - raw has exact sign (Sterbenz in [0.25,1]); tie -> q=0.
            float d = __fadd_rn(0.5f, -raw);
            unsigned s = (unsigned)(__float_as_int(d) >> 31);
            // err = val - q exactly: val + (-1.0f masked); Sterbenz-exact.
            float err = __fadd_rn(val, __uint_as_float(s & 0xBF800000u));
            err = active ? err : 0.0f;   // inactive lanes feed zero padding

            if (active) {
                // output = 2*q - 1 in {-1,+1}
                orow[c] = __uint_as_float(0xBF800000u ^ (s & 0x80000000u));
                if (lane == 31) myrow[c] = err;   // hand off to next band
            }
            left = err;

            // Cross-lane propagation (1 step of slack before consumption).
            float sh = __shfl_up_sync(0xFFFFFFFFu, err, 1);
            const int pi = t + SKEW;
            float pv = (pi < W) ? prevrow[pi] : 0.0f;  // broadcast LDS
            if (lane == 0) sh = pv;                    // SEL, no branch
            r4 = r3; r3 = r2; r2 = r1; r1 = sh;
        }

        if (lane == 31) {
            __threadfence_block();        // release: STS before counter
            progress[w] = (unsigned)t;
        }
    }
}

extern "C" void kernel_launch(void* const* d_in, const int* in_sizes, int n_in,
                              void* d_out, int out_size) {
    (void)in_sizes; (void)n_in; (void)out_size;
    const float* x = (const float*)d_in[0];
    float* out = (float*)d_out;
    fs_dither_kernel<<<NPLANES, NWARPS * 32>>>(x, out);
}

// round 14
// speedup vs baseline: 2.0395x; 1.1340x over previous
#include <cuda_runtime.h>

#define W 512
#define H 512
#define NPLANES 96
#define SKEW 2               // minimal skew: lane l -> col c = t - 2l
#define NWARPS 16            // one band (32 rows) per warp, whole plane per block
#define CH 16                // columns per sync chunk
#define LAG 64               // 32 rows * SKEW: producer lead needed by consumer
#define NSTEP_PAD 576        // 512 + 2*31 = 574, padded to 36 chunks of 16
#define NCHUNK (NSTEP_PAD / CH)

// Floyd-Steinberg 1-bit error diffusion.
// Codegen-identical to the reproducible 260us kernel (full #pragma unroll on
// the 16-step chunk — ptxas front-batches the 16 independent LDGs, regs=64;
// the rounds that used "#pragma unroll 4" all fell to 380-470us) with ONE
// semantic change: skew 3 -> 2, shortening the critical path from 2285 to
// 1774 steps (-22%). R9 already showed skew-2 scaling by ~0.8x within the
// unroll-4 codegen class; this applies it within the fast class.
// Skew-2 delay line: at step t lane l consumes
//   e_ur = r1 (row-above err at col c+1, shfl'd at end of step t-1)
//   e_u  = r2 (col c,   shfl'd at t-2)
//   e_ul = r3 (col c-1, shfl'd at t-3)
// Lane 0 substitutes prevrow[t+2] into the shfl each step.
__global__ void __launch_bounds__(NWARPS * 32, 1)
fs_dither_kernel(const float* __restrict__ x, float* __restrict__ out) {
    __shared__ float errbuf[NWARPS][W];
    __shared__ float zbuf[W];
    __shared__ volatile unsigned progress[NWARPS];

    const int tid = threadIdx.x;
    const int w = tid >> 5;
    const int lane = tid & 31;
    const int plane = blockIdx.x;

    const float* __restrict__ xp = x + (size_t)plane * (H * W);
    float* __restrict__ op = out + (size_t)plane * (H * W);

    for (int i = tid; i < W; i += NWARPS * 32) zbuf[i] = 0.0f;
    if (tid < NWARPS) progress[tid] = 0u;
    __syncthreads();

    const float* __restrict__ prevrow = (w == 0) ? zbuf : errbuf[w - 1];
    float* __restrict__ myrow = errbuf[w];

    const int row = w * 32 + lane;
    const float* __restrict__ xrow = xp + (size_t)row * W;
    float* __restrict__ orow = op + (size_t)row * W;

    float r1 = 0.0f, r2 = 0.0f, r3 = 0.0f;
    float left = 0.0f;

    int t = 0;
    for (int k = 0; k < NCHUNK; ++k) {
        if (w != 0) {
            unsigned need = (unsigned)(t + CH + LAG);
            if (need > NSTEP_PAD) need = NSTEP_PAD;
            while (progress[w - 1] < need) { /* spin */ }
        }
        __syncwarp();
        __threadfence_block();   // acquire: producer's STS now visible

        if (k == 0 && lane == 0) {
            // e_ul(t=0) = prev[-1] = 0 (pad); e_u = prev[0]; e_ur = prev[1].
            r3 = 0.0f;
            r2 = prevrow[0];
            r1 = prevrow[1];
        }

        #pragma unroll
        for (int i = 0; i < CH; ++i, ++t) {
            const int c = t - SKEW * lane;
            const bool active = ((unsigned)c < (unsigned)W);
            const float e_ur = r1, e_u = r2, e_ul = r3;

            // Clamped-address load keeps inactive lanes branch-free (L1-hit).
            int cl = c < 0 ? 0 : (c > W - 1 ? W - 1 : c);
            float xv = __ldg(xrow + cl);

            // x = clip(x,-1,1); x01 = (x+1)/2  (exact, matches reference)
            xv = fminf(fmaxf(xv, -1.0f), 1.0f);
            float x01 = __fmul_rn(__fadd_rn(xv, 1.0f), 0.5f);

            // up = (1/16*e_ul + 5/16*e_u) + 3/16*e_ur  (reference order, no FMA)
            float u = __fadd_rn(__fadd_rn(__fmul_rn(0.0625f, e_ul),
                                          __fmul_rn(0.3125f, e_u)),
                                __fmul_rn(0.1875f, e_ur));
            float pre = __fadd_rn(x01, u);
            float raw = __fadd_rn(pre, __fmul_rn(0.4375f, left));
            float val = fminf(fmaxf(raw, 0.0f), 1.0f);

            // q = round-half-even(val), val in [0,1]  <=>  raw > 0.5.
            // d = 0.5 - raw has exact sign (Sterbenz in [0.25,1]); tie -> q=0.
            float d = __fadd_rn(0.5f, -raw);
            unsigned s = (unsigned)(__float_as_int(d) >> 31);
            // err = val - q exactly: val + (-1.0f masked); Sterbenz-exact.
            float err = __fadd_rn(val, __uint_as_float(s & 0xBF800000u));
            err = active ? err : 0.0f;   // inactive lanes feed zero padding

            if (active) {
                // output = 2*q - 1 in {-1,+1}
                orow[c] = __uint_as_float(0xBF800000u ^ (s & 0x80000000u));
                if (lane == 31) myrow[c] = err;   // hand off to next band
            }
            left = err;

            // Cross-lane propagation; lane 0 injects the prev band's err.
            float sh = __shfl_up_sync(0xFFFFFFFFu, err, 1);
            const int pi = t + SKEW;
            float pv = (pi < W) ? prevrow[pi] : 0.0f;  // broadcast LDS
            if (lane == 0) sh = pv;                    // SEL, no branch
            r3 = r2; r2 = r1; r1 = sh;
        }

        if (lane == 31) {
            __threadfence_block();        // release: STS before counter
            progress[w] = (unsigned)t;
        }
    }
}

extern "C" void kernel_launch(void* const* d_in, const int* in_sizes, int n_in,
                              void* d_out, int out_size) {
    (void)in_sizes; (void)n_in; (void)out_size;
    const float* x = (const float*)d_in[0];
    float* out = (float*)d_out;
    fs_dither_kernel<<<NPLANES, NWARPS * 32>>>(x, out);
}